// round 12
// baseline (speedup 1.0000x reference)
#include <cuda_runtime.h>
#include <cuda_bf16.h>
#include <stdint.h>
#include <math.h>

#define NB 32
#define CC 256
#define HW 3136
#define PI_HALF 1.57079632679489662f

__device__ __nv_bfloat16 g_xh[NB][CC][HW];   // x hi, overwritten by t6 hi
__device__ __nv_bfloat16 g_xl[NB][CC][HW];   // x lo, overwritten by t6 lo
__device__ float g_gramp[3][NB][CC][CC];
__device__ float g_rowsum[NB][CC];
__device__ float g_u[NB][CC];
__device__ float g_v[NB][CC];
__device__ __nv_bfloat16 g_wph[CC][CC];
__device__ __nv_bfloat16 g_wpl[CC][CC];
__device__ __nv_bfloat16 g_t7h[NB][CC][CC];   // t7^T [d][c], bf16 hi
__device__ __nv_bfloat16 g_t7l[NB][CC][CC];   // t7^T [d][c], bf16 lo

__device__ __forceinline__ uint32_t smem_u32(const void* p) {
    uint32_t a;
    asm("{ .reg .u64 t; cvta.to.shared.u64 t, %1; cvt.u32.u64 %0, t; }"
        : "=r"(a) : "l"(p));
    return a;
}
__device__ __forceinline__ void cpa(uint32_t s, const void* g) {
    asm volatile("cp.async.cg.shared.global [%0], [%1], 16;" :: "r"(s), "l"(g));
}
#define CPA_COMMIT() asm volatile("cp.async.commit_group;" ::: "memory")
#define CPA_WAIT0()  asm volatile("cp.async.wait_group 0;" ::: "memory")

__device__ __forceinline__ void ldsm4(uint32_t r[4], uint32_t a) {
    asm volatile("ldmatrix.sync.aligned.m8n8.x4.shared.b16 {%0,%1,%2,%3}, [%4];"
                 : "=r"(r[0]), "=r"(r[1]), "=r"(r[2]), "=r"(r[3]) : "r"(a));
}
__device__ __forceinline__ void ldsm4t(uint32_t r[4], uint32_t a) {
    asm volatile("ldmatrix.sync.aligned.m8n8.x4.trans.shared.b16 {%0,%1,%2,%3}, [%4];"
                 : "=r"(r[0]), "=r"(r[1]), "=r"(r[2]), "=r"(r[3]) : "r"(a));
}
__device__ __forceinline__ void mma_bf16(float c[4], const uint32_t a[4],
                                         const uint32_t b[2]) {
    asm volatile(
        "mma.sync.aligned.m16n8k16.row.col.f32.bf16.bf16.f32 "
        "{%0,%1,%2,%3}, {%4,%5,%6,%7}, {%8,%9}, {%0,%1,%2,%3};"
        : "+f"(c[0]), "+f"(c[1]), "+f"(c[2]), "+f"(c[3])
        : "r"(a[0]), "r"(a[1]), "r"(a[2]), "r"(a[3]), "r"(b[0]), "r"(b[1]));
}
__device__ __forceinline__ uint32_t pk2(__nv_bfloat16 a, __nv_bfloat16 b) {
    unsigned short ua = *(unsigned short*)&a, ub = *(unsigned short*)&b;
    return (uint32_t)ua | ((uint32_t)ub << 16);
}
__device__ __forceinline__ float bflo(uint32_t v) {
    unsigned short u = (unsigned short)(v & 0xffffu);
    return __bfloat162float(*(__nv_bfloat16*)&u);
}
__device__ __forceinline__ float bfhi(uint32_t v) {
    unsigned short u = (unsigned short)(v >> 16);
    return __bfloat162float(*(__nv_bfloat16*)&u);
}

// ---- prep: x -> bf16 hi/lo + rowsums ----------------------------------------
__global__ void k_prep(const float* __restrict__ x) {
    const int n = blockIdx.y, c = blockIdx.x, t = threadIdx.x;
    const float4* row = (const float4*)(x + ((size_t)n * CC + c) * HW);
    uint2* oh = (uint2*)&g_xh[n][c][0];
    uint2* ol = (uint2*)&g_xl[n][c][0];
    float s = 0.f;
    for (int u = t; u < HW / 4; u += 256) {
        float4 v = row[u];
        s += v.x + v.y + v.z + v.w;
        __nv_bfloat16 h0 = __float2bfloat16(v.x), h1 = __float2bfloat16(v.y);
        __nv_bfloat16 h2 = __float2bfloat16(v.z), h3 = __float2bfloat16(v.w);
        uint2 ph, pl;
        ph.x = pk2(h0, h1); ph.y = pk2(h2, h3);
        pl.x = pk2(__float2bfloat16(v.x - __bfloat162float(h0)),
                   __float2bfloat16(v.y - __bfloat162float(h1)));
        pl.y = pk2(__float2bfloat16(v.z - __bfloat162float(h2)),
                   __float2bfloat16(v.w - __bfloat162float(h3)));
        oh[u] = ph; ol[u] = pl;
    }
#pragma unroll
    for (int o = 16; o; o >>= 1) s += __shfl_down_sync(0xffffffffu, s, o);
    __shared__ float red[8];
    if ((t & 31) == 0) red[t >> 5] = s;
    __syncthreads();
    if (t == 0) {
        float tt = 0.f;
#pragma unroll
        for (int q = 0; q < 8; q++) tt += red[q];
        g_rowsum[n][c] = tt;
    }
}

__global__ void k_wprep(const float* __restrict__ w) {
    const int o = blockIdx.x, i = threadIdx.x;
    const float v = w[o * 256 + i];
    __nv_bfloat16 h = __float2bfloat16(v);
    g_wph[o][i] = h;
    g_wpl[o][i] = __float2bfloat16(v - __bfloat162float(h));
}

__global__ void k_uv(const float* __restrict__ Wg1, const float* __restrict__ Wg2) {
    const int n = blockIdx.x, t = threadIdx.x;
    __shared__ float ss[256];
    ss[t] = g_rowsum[n][t];
    __syncthreads();
    const int g = t >> 5, r = t & 31;
    float u = 0.f, v = 0.f;
#pragma unroll
    for (int i = 0; i < 32; i++) {
        u += Wg1[(g * 32 + r) * 32 + i] * ss[g * 32 + i];
        v += Wg2[(g * 32 + r) * 32 + i] * ss[g * 32 + i];
    }
    g_u[n][t] = u;
    g_v[n][t] = v;
}

// ---- Gram = x x^T, symmetric-tile, K-split x3 (round-7 pipeline) ------------
#define GSTRIDE 80u
#define GCH 10240
#define GRAM_SMEM (8 * GCH)

__global__ __launch_bounds__(256, 2) void k_gram() {
    extern __shared__ char sm[];
    const int q = blockIdx.x, n = blockIdx.y, ks = blockIdx.z;
    const int c0 = (q == 1) ? 128 : 0;
    const int d0 = (q == 0) ? 0 : 128;
    const bool diag = (q < 2);
    const int tid = threadIdx.x, lane = tid & 31, wid = tid >> 5;
    const int m0w = (wid & 1) * 64, n0w = (wid >> 1) * 32;
    const uint32_t smb = smem_u32(sm);

    const char* gAh = (const char*)&g_xh[n][c0][0];
    const char* gAl = (const char*)&g_xl[n][c0][0];
    const char* gBh = (const char*)&g_xh[n][d0][0];
    const char* gBl = (const char*)&g_xl[n][d0][0];

    const int lr = tid >> 1, ls = (tid & 1) * 32;
    const int a_r = lane & 15, a_kb = (lane >> 4) * 16;
    const int b_r = (lane & 7) + 8 * (lane >> 4);
    const int b_kb = ((lane >> 3) & 1) * 16;

    float acc[4][4][4];
#pragma unroll
    for (int i = 0; i < 4; i++)
#pragma unroll
        for (int j = 0; j < 4; j++)
#pragma unroll
            for (int p = 0; p < 4; p++) acc[i][j][p] = 0.f;

    const int ck0 = ks * 33;
    const int nck = (ks < 2) ? 33 : 32;
    const uint32_t so = (uint32_t)lr * GSTRIDE + ls;

    auto issueG = [&](int ci, int buf) {
        const size_t go = (size_t)lr * (HW * 2) + (size_t)(ck0 + ci) * 64 + ls;
        const uint32_t aH = smb + (buf * 2 + 0) * GCH + so;
        const uint32_t aL = smb + (buf * 2 + 1) * GCH + so;
        cpa(aH, gAh + go); cpa(aH + 16, gAh + go + 16);
        cpa(aL, gAl + go); cpa(aL + 16, gAl + go + 16);
        if (!diag) {
            const uint32_t bH = smb + 4 * GCH + (buf * 2 + 0) * GCH + so;
            const uint32_t bL = smb + 4 * GCH + (buf * 2 + 1) * GCH + so;
            cpa(bH, gBh + go); cpa(bH + 16, gBh + go + 16);
            cpa(bL, gBl + go); cpa(bL + 16, gBl + go + 16);
        }
    };

    issueG(0, 0);
    CPA_COMMIT();

    for (int ci = 0; ci < nck; ci++) {
        const int buf = ci & 1;
        CPA_WAIT0();
        __syncthreads();
        if (ci < nck - 1) { issueG(ci + 1, buf ^ 1); CPA_COMMIT(); }

        const uint32_t aHb = smb + (buf * 2 + 0) * GCH;
        const uint32_t aLb = smb + (buf * 2 + 1) * GCH;
        const uint32_t bHb = diag ? aHb : smb + 4 * GCH + (buf * 2 + 0) * GCH;
        const uint32_t bLb = diag ? aLb : smb + 4 * GCH + (buf * 2 + 1) * GCH;
#pragma unroll
        for (int kk = 0; kk < 2; kk++) {
            const uint32_t kbo = kk * 32;
            uint32_t a[4][4], bh[4][2], bl[4][2];
#pragma unroll
            for (int mt = 0; mt < 4; mt++)
                ldsm4(a[mt], aHb + (uint32_t)(m0w + mt * 16 + a_r) * GSTRIDE + a_kb + kbo);
#pragma unroll
            for (int nt2 = 0; nt2 < 2; nt2++) {
                const uint32_t ro = (uint32_t)(n0w + nt2 * 16 + b_r) * GSTRIDE + b_kb + kbo;
                uint32_t t[4];
                ldsm4(t, bHb + ro);
                bh[nt2 * 2][0] = t[0]; bh[nt2 * 2][1] = t[1];
                bh[nt2 * 2 + 1][0] = t[2]; bh[nt2 * 2 + 1][1] = t[3];
                ldsm4(t, bLb + ro);
                bl[nt2 * 2][0] = t[0]; bl[nt2 * 2][1] = t[1];
                bl[nt2 * 2 + 1][0] = t[2]; bl[nt2 * 2 + 1][1] = t[3];
            }
#pragma unroll
            for (int mt = 0; mt < 4; mt++)
#pragma unroll
                for (int nt = 0; nt < 4; nt++) {
                    mma_bf16(acc[mt][nt], a[mt], bh[nt]);
                    mma_bf16(acc[mt][nt], a[mt], bl[nt]);
                }
#pragma unroll
            for (int mt = 0; mt < 4; mt++)
                ldsm4(a[mt], aLb + (uint32_t)(m0w + mt * 16 + a_r) * GSTRIDE + a_kb + kbo);
#pragma unroll
            for (int mt = 0; mt < 4; mt++)
#pragma unroll
                for (int nt = 0; nt < 4; nt++)
                    mma_bf16(acc[mt][nt], a[mt], bh[nt]);
        }
        __syncthreads();
    }

    float* gout = &g_gramp[ks][n][0][0];
#pragma unroll
    for (int mt = 0; mt < 4; mt++)
#pragma unroll
        for (int h = 0; h < 2; h++) {
            const int c = c0 + m0w + mt * 16 + (lane >> 2) + h * 8;
#pragma unroll
            for (int nt = 0; nt < 4; nt++) {
                const int d = d0 + n0w + nt * 8 + (lane & 3) * 2;
                const float v0 = acc[mt][nt][h * 2], v1 = acc[mt][nt][h * 2 + 1];
                *(float2*)(gout + (size_t)c * CC + d) = make_float2(v0, v1);
                if (!diag) {
                    gout[(size_t)d * CC + c] = v0;
                    gout[(size_t)(d + 1) * CC + c] = v1;
                }
            }
        }
}

// ---- t7^T (split bf16, pre-scaled by 1/(56*16)) ------------------------------
__global__ void k_t7(const float* __restrict__ Wg1, const float* __restrict__ bg1,
                     const float* __restrict__ Wg2, const float* __restrict__ bg2,
                     const float* __restrict__ p7w) {
    __shared__ float W1s[32][33], W2s[32][33], Gs[32][33], Ms[32][33];
    const int n = blockIdx.z, g = blockIdx.y, h = blockIdx.x;
    const int tx = threadIdx.x, ty = threadIdx.y;

    W1s[ty][tx] = Wg1[(g * 32 + ty) * 32 + tx];
    W2s[ty][tx] = Wg2[(h * 32 + ty) * 32 + tx];
    Gs[ty][tx]  = g_gramp[0][n][g * 32 + ty][h * 32 + tx]
                + g_gramp[1][n][g * 32 + ty][h * 32 + tx]
                + g_gramp[2][n][g * 32 + ty][h * 32 + tx];
    __syncthreads();

    float m = 0.f;
#pragma unroll
    for (int i = 0; i < 32; i++) m += W1s[ty][i] * Gs[i][tx];
    Ms[ty][tx] = m;
    __syncthreads();

    float t5 = 0.f;
#pragma unroll
    for (int j = 0; j < 32; j++) t5 += Ms[ty][j] * W2s[tx][j];

    const int c = g * 32 + ty, d = h * 32 + tx;
    const float b1 = bg1[c], b2 = bg2[d];
    t5 += b1 * g_v[n][d] + g_u[n][c] * b2 + (float)HW * b1 * b2;
    const float val = p7w[c * 256 + d] * t5 * (1.0f / 896.0f);

    __syncthreads();
    W1s[ty][tx] = val;
    __syncthreads();
    const float tv = W1s[tx][ty];
    const int dd = h * 32 + ty, cc = g * 32 + tx;
    __nv_bfloat16 hh = __float2bfloat16(tv);
    g_t7h[n][dd][cc] = hh;
    g_t7l[n][dd][cc] = __float2bfloat16(tv - __bfloat162float(hh));
}

// ---- GEMM body macro for k_t6 / k_out ----------------------------------------
// Lean issue: pointer-advance (no per-chunk 64-bit math), unroll-1 chunk loop.
#define ACH 20480
#define BCH 4096
#define TK_SMEM (4 * ACH + 4 * BCH)   // 98304

__device__ __forceinline__ uint32_t bswz(int row, int slot) {
    return (uint32_t)(row * 128 + ((slot ^ (row & 7)) << 4));
}

// requires in scope: acc[4][4][4], n, sx, tid, lane, m0w, n0w, smb
#define GEMM_256x64(Ah_, Al_)                                                      \
{                                                                                  \
    const int a_r = lane & 15, a_kb = (lane >> 4) * 16;                            \
    const int bt_r = (lane & 7) + 8 * ((lane >> 3) & 1);                           \
    const int bt_s = lane >> 4;                                                    \
    const int lb_r = tid >> 3, lb_s = tid & 7;                                     \
    const uint32_t boff = bswz(lb_r, lb_s);                                        \
    const char* pAh = (Ah_) + (size_t)tid * 512;                                   \
    const char* pAl = (Al_) + (size_t)tid * 512;                                   \
    const char* pBh = (const char*)&g_xh[n][0][sx * 64]                            \
                      + (size_t)lb_r * (HW * 2) + lb_s * 16;                       \
    const char* pBl = (const char*)&g_xl[n][0][sx * 64]                            \
                      + (size_t)lb_r * (HW * 2) + lb_s * 16;                       \
    const uint32_t aT = (uint32_t)tid * 80u;                                       \
    const uint32_t aH0 = smb + aT,           aL0 = smb + ACH + aT;                 \
    const uint32_t aH1 = smb + 2 * ACH + aT, aL1 = smb + 3 * ACH + aT;             \
    const uint32_t bH0 = smb + 4 * ACH + boff;                                     \
    const uint32_t bL0 = smb + 4 * ACH + BCH + boff;                               \
    const uint32_t bH1 = smb + 4 * ACH + 2 * BCH + boff;                           \
    const uint32_t bL1 = smb + 4 * ACH + 3 * BCH + boff;                           \
    auto issue = [&](int buf) {                                                    \
        const uint32_t aH = buf ? aH1 : aH0, aL = buf ? aL1 : aL0;                 \
        cpa(aH,      pAh);      cpa(aH + 16, pAh + 16);                            \
        cpa(aH + 32, pAh + 32); cpa(aH + 48, pAh + 48);                            \
        cpa(aL,      pAl);      cpa(aL + 16, pAl + 16);                            \
        cpa(aL + 32, pAl + 32); cpa(aL + 48, pAl + 48);                            \
        cpa(buf ? bH1 : bH0, pBh);                                                 \
        cpa(buf ? bL1 : bL0, pBl);                                                 \
        pAh += 64; pAl += 64;                                                      \
        pBh += 32 * (HW * 2); pBl += 32 * (HW * 2);                                \
    };                                                                             \
    issue(0);                                                                      \
    CPA_COMMIT();                                                                  \
    _Pragma("unroll 1")                                                            \
    for (int ci = 0; ci < 8; ci++) {                                               \
        const int buf = ci & 1;                                                    \
        CPA_WAIT0();                                                               \
        __syncthreads();                                                           \
        if (ci < 7) { issue(buf ^ 1); CPA_COMMIT(); }                              \
        const uint32_t aHb = smb + (buf * 2 + 0) * ACH;                            \
        const uint32_t aLb = smb + (buf * 2 + 1) * ACH;                            \
        const uint32_t bHb = smb + 4 * ACH + (buf * 2 + 0) * BCH;                  \
        const uint32_t bLb = smb + 4 * ACH + (buf * 2 + 1) * BCH;                  \
        _Pragma("unroll")                                                          \
        for (int kk = 0; kk < 2; kk++) {                                           \
            uint32_t a[4][4], bh[4][2], bl[4][2];                                  \
            _Pragma("unroll")                                                      \
            for (int mt = 0; mt < 4; mt++)                                         \
                ldsm4(a[mt], aHb + (uint32_t)(m0w + mt * 16 + a_r) * 80u           \
                                + a_kb + kk * 32);                                 \
            _Pragma("unroll")                                                      \
            for (int nt2 = 0; nt2 < 2; nt2++) {                                    \
                const int row = kk * 16 + bt_r;                                    \
                const int slot = ((n0w + nt2 * 16) >> 3) + bt_s;                   \
                const uint32_t ro = bswz(row, slot);                               \
                uint32_t t[4];                                                     \
                ldsm4t(t, bHb + ro);                                               \
                bh[nt2 * 2][0] = t[0]; bh[nt2 * 2][1] = t[1];                      \
                bh[nt2 * 2 + 1][0] = t[2]; bh[nt2 * 2 + 1][1] = t[3];              \
                ldsm4t(t, bLb + ro);                                               \
                bl[nt2 * 2][0] = t[0]; bl[nt2 * 2][1] = t[1];                      \
                bl[nt2 * 2 + 1][0] = t[2]; bl[nt2 * 2 + 1][1] = t[3];              \
            }                                                                      \
            _Pragma("unroll")                                                      \
            for (int mt = 0; mt < 4; mt++)                                         \
                _Pragma("unroll")                                                  \
                for (int nt = 0; nt < 4; nt++) {                                   \
                    mma_bf16(acc[mt][nt], a[mt], bh[nt]);                          \
                    mma_bf16(acc[mt][nt], a[mt], bl[nt]);                          \
                }                                                                  \
            _Pragma("unroll")                                                      \
            for (int mt = 0; mt < 4; mt++)                                         \
                ldsm4(a[mt], aLb + (uint32_t)(m0w + mt * 16 + a_r) * 80u           \
                                + a_kb + kk * 32);                                 \
            _Pragma("unroll")                                                      \
            for (int mt = 0; mt < 4; mt++)                                         \
                _Pragma("unroll")                                                  \
                for (int nt = 0; nt < 4; nt++)                                     \
                    mma_bf16(acc[mt][nt], a[mt], bh[nt]);                          \
        }                                                                          \
        __syncthreads();                                                           \
    }                                                                              \
}

// ---- k_t6: t6 = max(Wp3 x + b, sin(pi/2 x)); overwrite g_xh/g_xl in place ---
__global__ __launch_bounds__(256, 2) void k_t6(const float* __restrict__ bp3) {
    extern __shared__ char sm[];
    const int n = blockIdx.y, sx = blockIdx.x;
    const int tid = threadIdx.x, lane = tid & 31, wid = tid >> 5;
    const int m0w = (wid >> 1) * 64, n0w = (wid & 1) * 32;
    const uint32_t smb = smem_u32(sm);

    float acc[4][4][4];
#pragma unroll
    for (int i = 0; i < 4; i++)
#pragma unroll
        for (int j = 0; j < 4; j++)
#pragma unroll
            for (int p = 0; p < 4; p++) acc[i][j][p] = 0.f;

    GEMM_256x64((const char*)&g_wph[0][0], (const char*)&g_wpl[0][0]);

#pragma unroll
    for (int mt = 0; mt < 4; mt++)
#pragma unroll
        for (int h = 0; h < 2; h++) {
            const int c = m0w + mt * 16 + (lane >> 2) + h * 8;
            const float bias = __ldg(&bp3[c]);
#pragma unroll
            for (int nt = 0; nt < 4; nt++) {
                const int j = n0w + nt * 8 + (lane & 3) * 2;
                uint32_t* ph = (uint32_t*)&g_xh[n][c][sx * 64 + j];
                uint32_t* pl = (uint32_t*)&g_xl[n][c][sx * 64 + j];
                const uint32_t vh = *ph, vl = *pl;
                const float x0 = bflo(vh) + bflo(vl);
                const float x1 = bfhi(vh) + bfhi(vl);
                const float t60 = fmaxf(acc[mt][nt][h * 2] + bias,
                                        __sinf(PI_HALF * x0));
                const float t61 = fmaxf(acc[mt][nt][h * 2 + 1] + bias,
                                        __sinf(PI_HALF * x1));
                __nv_bfloat16 h0 = __float2bfloat16(t60);
                __nv_bfloat16 h1 = __float2bfloat16(t61);
                *ph = pk2(h0, h1);
                *pl = pk2(__float2bfloat16(t60 - __bfloat162float(h0)),
                          __float2bfloat16(t61 - __bfloat162float(h1)));
            }
        }
}

// ---- k_out: out = t7^T @ t6 ---------------------------------------------------
__global__ __launch_bounds__(256, 2) void k_out(float* __restrict__ out) {
    extern __shared__ char sm[];
    const int n = blockIdx.y, sx = blockIdx.x;
    const int tid = threadIdx.x, lane = tid & 31, wid = tid >> 5;
    const int m0w = (wid >> 1) * 64, n0w = (wid & 1) * 32;
    const uint32_t smb = smem_u32(sm);

    float acc[4][4][4];
#pragma unroll
    for (int i = 0; i < 4; i++)
#pragma unroll
        for (int j = 0; j < 4; j++)
#pragma unroll
            for (int p = 0; p < 4; p++) acc[i][j][p] = 0.f;

    GEMM_256x64((const char*)&g_t7h[n][0][0], (const char*)&g_t7l[n][0][0]);

    float* ob = out + (size_t)n * CC * HW + sx * 64;
#pragma unroll
    for (int mt = 0; mt < 4; mt++)
#pragma unroll
        for (int h = 0; h < 2; h++) {
            const int d = m0w + mt * 16 + (lane >> 2) + h * 8;
#pragma unroll
            for (int nt = 0; nt < 4; nt++) {
                const int j = n0w + nt * 8 + (lane & 3) * 2;
                *(float2*)(ob + (size_t)d * HW + j) =
                    make_float2(acc[mt][nt][h * 2], acc[mt][nt][h * 2 + 1]);
            }
        }
}

extern "C" void kernel_launch(void* const* d_in, const int* in_sizes, int n_in,
                              void* d_out, int out_size) {
    (void)in_sizes; (void)n_in; (void)out_size;
    const float* x   = (const float*)d_in[0];
    const float* Wp3 = (const float*)d_in[1];
    const float* bp3 = (const float*)d_in[2];
    const float* Wg1 = (const float*)d_in[3];
    const float* bg1 = (const float*)d_in[4];
    const float* Wg2 = (const float*)d_in[5];
    const float* bg2 = (const float*)d_in[6];
    const float* p7w = (const float*)d_in[7];
    float* out = (float*)d_out;

    cudaFuncSetAttribute(k_gram, cudaFuncAttributeMaxDynamicSharedMemorySize, GRAM_SMEM);
    cudaFuncSetAttribute(k_t6,   cudaFuncAttributeMaxDynamicSharedMemorySize, TK_SMEM);
    cudaFuncSetAttribute(k_out,  cudaFuncAttributeMaxDynamicSharedMemorySize, TK_SMEM);

    k_wprep<<<256, 256>>>(Wp3);
    k_prep<<<dim3(256, 32), 256>>>(x);
    k_uv<<<32, 256>>>(Wg1, Wg2);
    k_gram<<<dim3(3, 32, 3), 256, GRAM_SMEM>>>();
    k_t7<<<dim3(8, 8, 32), dim3(32, 32)>>>(Wg1, bg1, Wg2, bg2, p7w);
    k_t6<<<dim3(49, 32), 256, TK_SMEM>>>(bp3);
    k_out<<<dim3(49, 32), 256, TK_SMEM>>>(out);
}

// round 13
// speedup vs baseline: 3.4119x; 3.4119x over previous
#include <cuda_runtime.h>
#include <cuda_bf16.h>
#include <stdint.h>
#include <math.h>

#define NB 32
#define CC 256
#define HW 3136
#define PI_HALF 1.57079632679489662f

__device__ __nv_bfloat16 g_xh[NB][CC][HW];
__device__ __nv_bfloat16 g_xl[NB][CC][HW];
__device__ float g_gramp[3][NB][CC][CC];
__device__ float g_rowsum[NB][CC];
__device__ float g_u[NB][CC];
__device__ float g_v[NB][CC];
__device__ __nv_bfloat16 g_wph[CC][CC];
__device__ __nv_bfloat16 g_wpl[CC][CC];
__device__ __nv_bfloat16 g_t7h[NB][CC][CC];   // t7^T [d][c], bf16 hi
__device__ __nv_bfloat16 g_t7l[NB][CC][CC];   // t7^T [d][c], bf16 lo

__device__ __forceinline__ uint32_t smem_u32(const void* p) {
    uint32_t a;
    asm("{ .reg .u64 t; cvta.to.shared.u64 t, %1; cvt.u32.u64 %0, t; }"
        : "=r"(a) : "l"(p));
    return a;
}
__device__ __forceinline__ void cpa(uint32_t s, const void* g) {
    asm volatile("cp.async.cg.shared.global [%0], [%1], 16;" :: "r"(s), "l"(g));
}
#define CPA_COMMIT() asm volatile("cp.async.commit_group;" ::: "memory")
#define CPA_WAIT0()  asm volatile("cp.async.wait_group 0;" ::: "memory")

__device__ __forceinline__ void ldsm4(uint32_t r[4], uint32_t a) {
    asm volatile("ldmatrix.sync.aligned.m8n8.x4.shared.b16 {%0,%1,%2,%3}, [%4];"
                 : "=r"(r[0]), "=r"(r[1]), "=r"(r[2]), "=r"(r[3]) : "r"(a));
}
__device__ __forceinline__ void ldsm4t(uint32_t r[4], uint32_t a) {
    asm volatile("ldmatrix.sync.aligned.m8n8.x4.trans.shared.b16 {%0,%1,%2,%3}, [%4];"
                 : "=r"(r[0]), "=r"(r[1]), "=r"(r[2]), "=r"(r[3]) : "r"(a));
}
__device__ __forceinline__ void mma_bf16(float c[4], const uint32_t a[4],
                                         const uint32_t b[2]) {
    asm volatile(
        "mma.sync.aligned.m16n8k16.row.col.f32.bf16.bf16.f32 "
        "{%0,%1,%2,%3}, {%4,%5,%6,%7}, {%8,%9}, {%0,%1,%2,%3};"
        : "+f"(c[0]), "+f"(c[1]), "+f"(c[2]), "+f"(c[3])
        : "r"(a[0]), "r"(a[1]), "r"(a[2]), "r"(a[3]), "r"(b[0]), "r"(b[1]));
}
__device__ __forceinline__ uint32_t pk2(__nv_bfloat16 a, __nv_bfloat16 b) {
    unsigned short ua = *(unsigned short*)&a, ub = *(unsigned short*)&b;
    return (uint32_t)ua | ((uint32_t)ub << 16);
}
__device__ __forceinline__ float bflo(uint32_t v) {
    unsigned short u = (unsigned short)(v & 0xffffu);
    return __bfloat162float(*(__nv_bfloat16*)&u);
}
__device__ __forceinline__ float bfhi(uint32_t v) {
    unsigned short u = (unsigned short)(v >> 16);
    return __bfloat162float(*(__nv_bfloat16*)&u);
}

// ---- prep: x -> bf16 hi/lo + rowsums ----------------------------------------
__global__ void k_prep(const float* __restrict__ x) {
    const int n = blockIdx.y, c = blockIdx.x, t = threadIdx.x;
    const float4* row = (const float4*)(x + ((size_t)n * CC + c) * HW);
    uint2* oh = (uint2*)&g_xh[n][c][0];
    uint2* ol = (uint2*)&g_xl[n][c][0];
    float s = 0.f;
    for (int u = t; u < HW / 4; u += 256) {
        float4 v = row[u];
        s += v.x + v.y + v.z + v.w;
        __nv_bfloat16 h0 = __float2bfloat16(v.x), h1 = __float2bfloat16(v.y);
        __nv_bfloat16 h2 = __float2bfloat16(v.z), h3 = __float2bfloat16(v.w);
        uint2 ph, pl;
        ph.x = pk2(h0, h1); ph.y = pk2(h2, h3);
        pl.x = pk2(__float2bfloat16(v.x - __bfloat162float(h0)),
                   __float2bfloat16(v.y - __bfloat162float(h1)));
        pl.y = pk2(__float2bfloat16(v.z - __bfloat162float(h2)),
                   __float2bfloat16(v.w - __bfloat162float(h3)));
        oh[u] = ph; ol[u] = pl;
    }
#pragma unroll
    for (int o = 16; o; o >>= 1) s += __shfl_down_sync(0xffffffffu, s, o);
    __shared__ float red[8];
    if ((t & 31) == 0) red[t >> 5] = s;
    __syncthreads();
    if (t == 0) {
        float tt = 0.f;
#pragma unroll
        for (int q = 0; q < 8; q++) tt += red[q];
        g_rowsum[n][c] = tt;
    }
}

__global__ void k_wprep(const float* __restrict__ w) {
    const int o = blockIdx.x, i = threadIdx.x;
    const float v = w[o * 256 + i];
    __nv_bfloat16 h = __float2bfloat16(v);
    g_wph[o][i] = h;
    g_wpl[o][i] = __float2bfloat16(v - __bfloat162float(h));
}

__global__ void k_uv(const float* __restrict__ Wg1, const float* __restrict__ Wg2) {
    const int n = blockIdx.x, t = threadIdx.x;
    __shared__ float ss[256];
    ss[t] = g_rowsum[n][t];
    __syncthreads();
    const int g = t >> 5, r = t & 31;
    float u = 0.f, v = 0.f;
#pragma unroll
    for (int i = 0; i < 32; i++) {
        u += Wg1[(g * 32 + r) * 32 + i] * ss[g * 32 + i];
        v += Wg2[(g * 32 + r) * 32 + i] * ss[g * 32 + i];
    }
    g_u[n][t] = u;
    g_v[n][t] = v;
}

// ---- Gram = x x^T, symmetric-tile, K-split x3 (round-7 pipeline, unchanged) --
#define GSTRIDE 80u
#define GCH 10240
#define GRAM_SMEM (8 * GCH)

__global__ __launch_bounds__(256, 2) void k_gram() {
    extern __shared__ char sm[];
    const int q = blockIdx.x, n = blockIdx.y, ks = blockIdx.z;
    const int c0 = (q == 1) ? 128 : 0;
    const int d0 = (q == 0) ? 0 : 128;
    const bool diag = (q < 2);
    const int tid = threadIdx.x, lane = tid & 31, wid = tid >> 5;
    const int m0w = (wid & 1) * 64, n0w = (wid >> 1) * 32;
    const uint32_t smb = smem_u32(sm);

    const char* gAh = (const char*)&g_xh[n][c0][0];
    const char* gAl = (const char*)&g_xl[n][c0][0];
    const char* gBh = (const char*)&g_xh[n][d0][0];
    const char* gBl = (const char*)&g_xl[n][d0][0];

    const int lr = tid >> 1, ls = (tid & 1) * 32;
    const int a_r = lane & 15, a_kb = (lane >> 4) * 16;
    const int b_r = (lane & 7) + 8 * (lane >> 4);
    const int b_kb = ((lane >> 3) & 1) * 16;

    float acc[4][4][4];
#pragma unroll
    for (int i = 0; i < 4; i++)
#pragma unroll
        for (int j = 0; j < 4; j++)
#pragma unroll
            for (int p = 0; p < 4; p++) acc[i][j][p] = 0.f;

    const int ck0 = ks * 33;
    const int nck = (ks < 2) ? 33 : 32;
    const uint32_t so = (uint32_t)lr * GSTRIDE + ls;

    auto issueG = [&](int ci, int buf) {
        const size_t go = (size_t)lr * (HW * 2) + (size_t)(ck0 + ci) * 64 + ls;
        const uint32_t aH = smb + (buf * 2 + 0) * GCH + so;
        const uint32_t aL = smb + (buf * 2 + 1) * GCH + so;
        cpa(aH, gAh + go); cpa(aH + 16, gAh + go + 16);
        cpa(aL, gAl + go); cpa(aL + 16, gAl + go + 16);
        if (!diag) {
            const uint32_t bH = smb + 4 * GCH + (buf * 2 + 0) * GCH + so;
            const uint32_t bL = smb + 4 * GCH + (buf * 2 + 1) * GCH + so;
            cpa(bH, gBh + go); cpa(bH + 16, gBh + go + 16);
            cpa(bL, gBl + go); cpa(bL + 16, gBl + go + 16);
        }
    };

    issueG(0, 0);
    CPA_COMMIT();

    for (int ci = 0; ci < nck; ci++) {
        const int buf = ci & 1;
        CPA_WAIT0();
        __syncthreads();
        if (ci < nck - 1) { issueG(ci + 1, buf ^ 1); CPA_COMMIT(); }

        const uint32_t aHb = smb + (buf * 2 + 0) * GCH;
        const uint32_t aLb = smb + (buf * 2 + 1) * GCH;
        const uint32_t bHb = diag ? aHb : smb + 4 * GCH + (buf * 2 + 0) * GCH;
        const uint32_t bLb = diag ? aLb : smb + 4 * GCH + (buf * 2 + 1) * GCH;
#pragma unroll
        for (int kk = 0; kk < 2; kk++) {
            const uint32_t kbo = kk * 32;
            uint32_t a[4][4], bh[4][2], bl[4][2];
#pragma unroll
            for (int mt = 0; mt < 4; mt++)
                ldsm4(a[mt], aHb + (uint32_t)(m0w + mt * 16 + a_r) * GSTRIDE + a_kb + kbo);
#pragma unroll
            for (int nt2 = 0; nt2 < 2; nt2++) {
                const uint32_t ro = (uint32_t)(n0w + nt2 * 16 + b_r) * GSTRIDE + b_kb + kbo;
                uint32_t t[4];
                ldsm4(t, bHb + ro);
                bh[nt2 * 2][0] = t[0]; bh[nt2 * 2][1] = t[1];
                bh[nt2 * 2 + 1][0] = t[2]; bh[nt2 * 2 + 1][1] = t[3];
                ldsm4(t, bLb + ro);
                bl[nt2 * 2][0] = t[0]; bl[nt2 * 2][1] = t[1];
                bl[nt2 * 2 + 1][0] = t[2]; bl[nt2 * 2 + 1][1] = t[3];
            }
#pragma unroll
            for (int mt = 0; mt < 4; mt++)
#pragma unroll
                for (int nt = 0; nt < 4; nt++) {
                    mma_bf16(acc[mt][nt], a[mt], bh[nt]);
                    mma_bf16(acc[mt][nt], a[mt], bl[nt]);
                }
#pragma unroll
            for (int mt = 0; mt < 4; mt++)
                ldsm4(a[mt], aLb + (uint32_t)(m0w + mt * 16 + a_r) * GSTRIDE + a_kb + kbo);
#pragma unroll
            for (int mt = 0; mt < 4; mt++)
#pragma unroll
                for (int nt = 0; nt < 4; nt++)
                    mma_bf16(acc[mt][nt], a[mt], bh[nt]);
        }
        __syncthreads();
    }

    float* gout = &g_gramp[ks][n][0][0];
#pragma unroll
    for (int mt = 0; mt < 4; mt++)
#pragma unroll
        for (int h = 0; h < 2; h++) {
            const int c = c0 + m0w + mt * 16 + (lane >> 2) + h * 8;
#pragma unroll
            for (int nt = 0; nt < 4; nt++) {
                const int d = d0 + n0w + nt * 8 + (lane & 3) * 2;
                const float v0 = acc[mt][nt][h * 2], v1 = acc[mt][nt][h * 2 + 1];
                *(float2*)(gout + (size_t)c * CC + d) = make_float2(v0, v1);
                if (!diag) {
                    gout[(size_t)d * CC + c] = v0;
                    gout[(size_t)(d + 1) * CC + c] = v1;
                }
            }
        }
}

// ---- t7^T (split bf16, pre-scaled by 1/(56*16)) ------------------------------
__global__ void k_t7(const float* __restrict__ Wg1, const float* __restrict__ bg1,
                     const float* __restrict__ Wg2, const float* __restrict__ bg2,
                     const float* __restrict__ p7w) {
    __shared__ float W1s[32][33], W2s[32][33], Gs[32][33], Ms[32][33];
    const int n = blockIdx.z, g = blockIdx.y, h = blockIdx.x;
    const int tx = threadIdx.x, ty = threadIdx.y;

    W1s[ty][tx] = Wg1[(g * 32 + ty) * 32 + tx];
    W2s[ty][tx] = Wg2[(h * 32 + ty) * 32 + tx];
    Gs[ty][tx]  = g_gramp[0][n][g * 32 + ty][h * 32 + tx]
                + g_gramp[1][n][g * 32 + ty][h * 32 + tx]
                + g_gramp[2][n][g * 32 + ty][h * 32 + tx];
    __syncthreads();

    float m = 0.f;
#pragma unroll
    for (int i = 0; i < 32; i++) m += W1s[ty][i] * Gs[i][tx];
    Ms[ty][tx] = m;
    __syncthreads();

    float t5 = 0.f;
#pragma unroll
    for (int j = 0; j < 32; j++) t5 += Ms[ty][j] * W2s[tx][j];

    const int c = g * 32 + ty, d = h * 32 + tx;
    const float b1 = bg1[c], b2 = bg2[d];
    t5 += b1 * g_v[n][d] + g_u[n][c] * b2 + (float)HW * b1 * b2;
    const float val = p7w[c * 256 + d] * t5 * (1.0f / 896.0f);

    __syncthreads();
    W1s[ty][tx] = val;
    __syncthreads();
    const float tv = W1s[tx][ty];
    const int dd = h * 32 + ty, cc = g * 32 + tx;
    __nv_bfloat16 hh = __float2bfloat16(tv);
    g_t7h[n][dd][cc] = hh;
    g_t7l[n][dd][cc] = __float2bfloat16(tv - __bfloat162float(hh));
}

// ---- fused: N=128 (two 64-col panels), 512 threads, 1 CTA/SM -----------------
// B panels resident: hi p0 @0, hi p1 @FPAN, lo p0 @2FPAN, lo p1 @3FPAN.
// A chunks (k=16, stride 48) double buffered at 4*FPAN.
#define FPAN 32768
#define FACH 12288
#define FUSED_SMEM (4 * FPAN + 4 * FACH)   // 180224

__device__ __forceinline__ uint32_t bswz(int row, int slot) {
    return (uint32_t)(row * 128 + ((slot ^ (row & 7)) << 4));
}

__global__ __launch_bounds__(512, 1) void k_fused(const float* __restrict__ bp3,
                                                  float* __restrict__ out) {
    extern __shared__ char sm[];
    const int n = blockIdx.y, sx = blockIdx.x;
    const int tid = threadIdx.x, lane = tid & 31, wid = tid >> 5;
    const int m0w = (wid >> 2) * 64, n0w = (wid & 3) * 32;
    const uint32_t smb = smem_u32(sm);
    const bool tail = (sx == 24);   // cols 3072..3135 valid (64 of 128)

    {   // load B panels (x stripe, 256 k-rows x 128 cols hi/lo)
        const char* srcH = (const char*)&g_xh[n][0][0];
        const char* srcL = (const char*)&g_xl[n][0][0];
#pragma unroll
        for (int i = 0; i < 16; i++) {
            const int idx = tid + i * 512;
            const int half = idx >> 12, rest = idx & 4095;
            const int panel = rest >> 11, seg = rest & 2047;
            const int r = seg >> 3, s = seg & 7;
            if (tail && panel) continue;
            const uint32_t off = (uint32_t)(half * 2 + panel) * FPAN + bswz(r, s);
            const size_t g = (size_t)r * (HW * 2)
                           + (size_t)(sx * 128 + panel * 64) * 2 + s * 16;
            cpa(smb + off, (half ? srcL : srcH) + g);
        }
    }

    const int a_rr = tid >> 1, a_ss = (tid & 1) * 16;
    auto issueA = [&](int g1, int buf) {
        const char* Ah = (g1 < 16) ? (const char*)&g_wph[0][0] : (const char*)&g_t7h[n][0][0];
        const char* Al = (g1 < 16) ? (const char*)&g_wpl[0][0] : (const char*)&g_t7l[n][0][0];
        const int kb = (g1 & 15) * 32;
        const uint32_t ao = (uint32_t)a_rr * 48u + a_ss;
        const size_t ga = (size_t)a_rr * 512 + kb + a_ss;
        cpa(smb + 4 * FPAN + (buf * 2 + 0) * FACH + ao, Ah + ga);
        cpa(smb + 4 * FPAN + (buf * 2 + 1) * FACH + ao, Al + ga);
    };
    issueA(0, 0);
    CPA_COMMIT();

    float acc[4][4][4];
#pragma unroll
    for (int i = 0; i < 4; i++)
#pragma unroll
        for (int j = 0; j < 4; j++)
#pragma unroll
            for (int p = 0; p < 4; p++) acc[i][j][p] = 0.f;

    const int a_r = lane & 15, a_kb = (lane >> 4) * 16;
    const int bt_r = (lane & 7) + 8 * ((lane >> 3) & 1);
    const int bt_s = lane >> 4;

    for (int g = 0; g < 32; g++) {
        const int buf = g & 1;
        CPA_WAIT0();
        __syncthreads();
        if (g < 31) { issueA(g + 1, buf ^ 1); CPA_COMMIT(); }

        if (g == 16) {
            // stage0 epilogue: t6 = max(t3 + bias, sin(pi/2 x)); rewrite B panels
#pragma unroll
            for (int mt = 0; mt < 4; mt++)
#pragma unroll
                for (int h = 0; h < 2; h++) {
                    const int c = m0w + mt * 16 + (lane >> 2) + h * 8;
                    const float bias = __ldg(&bp3[c]);
#pragma unroll
                    for (int nt = 0; nt < 4; nt++) {
                        const int j = n0w + nt * 8 + (lane & 3) * 2;
                        const int panel = j >> 6, jn = j & 63;
                        const uint32_t off = bswz(c, jn >> 3) + (jn & 7) * 2;
                        uint32_t* ph = (uint32_t*)(sm + (size_t)panel * FPAN + off);
                        uint32_t* pl = (uint32_t*)(sm + (size_t)(2 + panel) * FPAN + off);
                        const uint32_t vh = *ph, vl = *pl;
                        const float x0 = bflo(vh) + bflo(vl);
                        const float x1 = bfhi(vh) + bfhi(vl);
                        const float t60 = fmaxf(acc[mt][nt][h * 2] + bias,
                                                __sinf(PI_HALF * x0));
                        const float t61 = fmaxf(acc[mt][nt][h * 2 + 1] + bias,
                                                __sinf(PI_HALF * x1));
                        __nv_bfloat16 h0 = __float2bfloat16(t60);
                        __nv_bfloat16 h1 = __float2bfloat16(t61);
                        *ph = pk2(h0, h1);
                        *pl = pk2(__float2bfloat16(t60 - __bfloat162float(h0)),
                                  __float2bfloat16(t61 - __bfloat162float(h1)));
                        acc[mt][nt][h * 2] = 0.f;
                        acc[mt][nt][h * 2 + 1] = 0.f;
                    }
                }
            __syncthreads();
        }

        const uint32_t aHb = smb + 4 * FPAN + (buf * 2 + 0) * FACH;
        const uint32_t aLb = smb + 4 * FPAN + (buf * 2 + 1) * FACH;
        const int kg = (g & 15) * 16;
        uint32_t a[4][4], bh[4][2], bl[4][2];
#pragma unroll
        for (int mt = 0; mt < 4; mt++)
            ldsm4(a[mt], aHb + (uint32_t)(m0w + mt * 16 + a_r) * 48u + a_kb);
#pragma unroll
        for (int nt2 = 0; nt2 < 2; nt2++) {
            const int jcol = n0w + nt2 * 16;
            const int panel = jcol >> 6;
            const int slot = ((jcol & 63) >> 3) + bt_s;
            const int row = kg + bt_r;
            const uint32_t ro = bswz(row, slot);
            uint32_t t[4];
            ldsm4t(t, smb + (uint32_t)panel * FPAN + ro);
            bh[nt2 * 2][0] = t[0]; bh[nt2 * 2][1] = t[1];
            bh[nt2 * 2 + 1][0] = t[2]; bh[nt2 * 2 + 1][1] = t[3];
            ldsm4t(t, smb + (uint32_t)(2 + panel) * FPAN + ro);
            bl[nt2 * 2][0] = t[0]; bl[nt2 * 2][1] = t[1];
            bl[nt2 * 2 + 1][0] = t[2]; bl[nt2 * 2 + 1][1] = t[3];
        }
#pragma unroll
        for (int mt = 0; mt < 4; mt++)
#pragma unroll
            for (int nt = 0; nt < 4; nt++) {
                mma_bf16(acc[mt][nt], a[mt], bh[nt]);
                mma_bf16(acc[mt][nt], a[mt], bl[nt]);
            }
#pragma unroll
        for (int mt = 0; mt < 4; mt++)
            ldsm4(a[mt], aLb + (uint32_t)(m0w + mt * 16 + a_r) * 48u + a_kb);
#pragma unroll
        for (int mt = 0; mt < 4; mt++)
#pragma unroll
            for (int nt = 0; nt < 4; nt++)
                mma_bf16(acc[mt][nt], a[mt], bh[nt]);
        __syncthreads();
    }

    float* ob = out + (size_t)n * CC * HW + (size_t)sx * 128;
#pragma unroll
    for (int mt = 0; mt < 4; mt++)
#pragma unroll
        for (int h = 0; h < 2; h++) {
            const int d = m0w + mt * 16 + (lane >> 2) + h * 8;
#pragma unroll
            for (int nt = 0; nt < 4; nt++) {
                const int j = n0w + nt * 8 + (lane & 3) * 2;
                if (!tail || j < 64)
                    *(float2*)(ob + (size_t)d * HW + j) =
                        make_float2(acc[mt][nt][h * 2], acc[mt][nt][h * 2 + 1]);
            }
        }
}

extern "C" void kernel_launch(void* const* d_in, const int* in_sizes, int n_in,
                              void* d_out, int out_size) {
    (void)in_sizes; (void)n_in; (void)out_size;
    const float* x   = (const float*)d_in[0];
    const float* Wp3 = (const float*)d_in[1];
    const float* bp3 = (const float*)d_in[2];
    const float* Wg1 = (const float*)d_in[3];
    const float* bg1 = (const float*)d_in[4];
    const float* Wg2 = (const float*)d_in[5];
    const float* bg2 = (const float*)d_in[6];
    const float* p7w = (const float*)d_in[7];
    float* out = (float*)d_out;

    cudaFuncSetAttribute(k_gram,  cudaFuncAttributeMaxDynamicSharedMemorySize, GRAM_SMEM);
    cudaFuncSetAttribute(k_fused, cudaFuncAttributeMaxDynamicSharedMemorySize, FUSED_SMEM);

    k_wprep<<<256, 256>>>(Wp3);
    k_prep<<<dim3(256, 32), 256>>>(x);
    k_uv<<<32, 256>>>(Wg1, Wg2);
    k_gram<<<dim3(3, 32, 3), 256, GRAM_SMEM>>>();
    k_t7<<<dim3(8, 8, 32), dim3(32, 32)>>>(Wg1, bg1, Wg2, bg2, p7w);
    k_fused<<<dim3(25, 32), 512, FUSED_SMEM>>>(bp3, out);
}

// round 14
// speedup vs baseline: 3.7175x; 1.0896x over previous
#include <cuda_runtime.h>
#include <cuda_bf16.h>
#include <stdint.h>
#include <math.h>

#define NB 32
#define CC 256
#define HW 3136
#define PI_HALF 1.57079632679489662f

__device__ __nv_bfloat16 g_xh[NB][CC][HW];
__device__ __nv_bfloat16 g_xl[NB][CC][HW];
__device__ float g_gramp[3][NB][CC][CC];
__device__ float g_rowsum[NB][CC];
__device__ float g_u[NB][CC];
__device__ float g_v[NB][CC];
// packed A operands: [hi/lo][chunk][256 rows * 24 bf16 (16 data + 8 pad)]
__device__ __nv_bfloat16 g_wpk[2][16][256 * 24];
__device__ __nv_bfloat16 g_t7k[NB][2][16][256 * 24];

__device__ __forceinline__ uint32_t smem_u32(const void* p) {
    uint32_t a;
    asm("{ .reg .u64 t; cvta.to.shared.u64 t, %1; cvt.u32.u64 %0, t; }"
        : "=r"(a) : "l"(p));
    return a;
}
__device__ __forceinline__ void cpa(uint32_t s, const void* g) {
    asm volatile("cp.async.cg.shared.global [%0], [%1], 16;" :: "r"(s), "l"(g));
}
#define CPA_COMMIT() asm volatile("cp.async.commit_group;" ::: "memory")
#define CPA_WAIT0()  asm volatile("cp.async.wait_group 0;" ::: "memory")

__device__ __forceinline__ void bulkcp(uint32_t dst, const void* src,
                                       uint32_t bytes, uint32_t mbar) {
    asm volatile(
        "cp.async.bulk.shared::cta.global.mbarrier::complete_tx::bytes "
        "[%0], [%1], %2, [%3];"
        :: "r"(dst), "l"(src), "r"(bytes), "r"(mbar) : "memory");
}
#define MBAR_INIT(a, c) asm volatile("mbarrier.init.shared.b64 [%0], %1;" :: "r"(a), "r"((uint32_t)(c)) : "memory")
#define MBAR_EXPECT(a, b) asm volatile("mbarrier.arrive.expect_tx.shared.b64 _, [%0], %1;" :: "r"(a), "r"((uint32_t)(b)) : "memory")
#define MBAR_WAIT(a, ph) do {                                                   \
    uint32_t _m = (a), _p = (uint32_t)(ph), _d;                                 \
    asm volatile("{\n\t.reg .pred p;\n\t"                                       \
        "mbarrier.try_wait.parity.acquire.cta.shared::cta.b64 p, [%1], %2;\n\t" \
        "selp.b32 %0, 1, 0, p;\n\t}" : "=r"(_d) : "r"(_m), "r"(_p) : "memory"); \
    if (!_d) { asm volatile("{\n\t.reg .pred P1;\n\tWL_%=:\n\t"                 \
        "mbarrier.try_wait.parity.acquire.cta.shared::cta.b64 P1, [%0], %1, 0x989680;\n\t" \
        "@P1 bra.uni WD_%=;\n\tbra.uni WL_%=;\n\tWD_%=:\n\t}"                   \
        :: "r"(_m), "r"(_p) : "memory"); }                                      \
} while (0)

__device__ __forceinline__ void ldsm4(uint32_t r[4], uint32_t a) {
    asm volatile("ldmatrix.sync.aligned.m8n8.x4.shared.b16 {%0,%1,%2,%3}, [%4];"
                 : "=r"(r[0]), "=r"(r[1]), "=r"(r[2]), "=r"(r[3]) : "r"(a));
}
__device__ __forceinline__ void ldsm4t(uint32_t r[4], uint32_t a) {
    asm volatile("ldmatrix.sync.aligned.m8n8.x4.trans.shared.b16 {%0,%1,%2,%3}, [%4];"
                 : "=r"(r[0]), "=r"(r[1]), "=r"(r[2]), "=r"(r[3]) : "r"(a));
}
__device__ __forceinline__ void mma_bf16(float c[4], const uint32_t a[4],
                                         const uint32_t b[2]) {
    asm volatile(
        "mma.sync.aligned.m16n8k16.row.col.f32.bf16.bf16.f32 "
        "{%0,%1,%2,%3}, {%4,%5,%6,%7}, {%8,%9}, {%0,%1,%2,%3};"
        : "+f"(c[0]), "+f"(c[1]), "+f"(c[2]), "+f"(c[3])
        : "r"(a[0]), "r"(a[1]), "r"(a[2]), "r"(a[3]), "r"(b[0]), "r"(b[1]));
}
__device__ __forceinline__ uint32_t pk2(__nv_bfloat16 a, __nv_bfloat16 b) {
    unsigned short ua = *(unsigned short*)&a, ub = *(unsigned short*)&b;
    return (uint32_t)ua | ((uint32_t)ub << 16);
}
__device__ __forceinline__ float bflo(uint32_t v) {
    unsigned short u = (unsigned short)(v & 0xffffu);
    return __bfloat162float(*(__nv_bfloat16*)&u);
}
__device__ __forceinline__ float bfhi(uint32_t v) {
    unsigned short u = (unsigned short)(v >> 16);
    return __bfloat162float(*(__nv_bfloat16*)&u);
}

// ---- prep: x -> bf16 hi/lo + rowsums ----------------------------------------
__global__ void k_prep(const float* __restrict__ x) {
    const int n = blockIdx.y, c = blockIdx.x, t = threadIdx.x;
    const float4* row = (const float4*)(x + ((size_t)n * CC + c) * HW);
    uint2* oh = (uint2*)&g_xh[n][c][0];
    uint2* ol = (uint2*)&g_xl[n][c][0];
    float s = 0.f;
    for (int u = t; u < HW / 4; u += 256) {
        float4 v = row[u];
        s += v.x + v.y + v.z + v.w;
        __nv_bfloat16 h0 = __float2bfloat16(v.x), h1 = __float2bfloat16(v.y);
        __nv_bfloat16 h2 = __float2bfloat16(v.z), h3 = __float2bfloat16(v.w);
        uint2 ph, pl;
        ph.x = pk2(h0, h1); ph.y = pk2(h2, h3);
        pl.x = pk2(__float2bfloat16(v.x - __bfloat162float(h0)),
                   __float2bfloat16(v.y - __bfloat162float(h1)));
        pl.y = pk2(__float2bfloat16(v.z - __bfloat162float(h2)),
                   __float2bfloat16(v.w - __bfloat162float(h3)));
        oh[u] = ph; ol[u] = pl;
    }
#pragma unroll
    for (int o = 16; o; o >>= 1) s += __shfl_down_sync(0xffffffffu, s, o);
    __shared__ float red[8];
    if ((t & 31) == 0) red[t >> 5] = s;
    __syncthreads();
    if (t == 0) {
        float tt = 0.f;
#pragma unroll
        for (int q = 0; q < 8; q++) tt += red[q];
        g_rowsum[n][c] = tt;
    }
}

__global__ void k_wprep(const float* __restrict__ w) {
    const int o = blockIdx.x, i = threadIdx.x;
    const float v = w[o * 256 + i];
    __nv_bfloat16 h = __float2bfloat16(v);
    g_wpk[0][i >> 4][o * 24 + (i & 15)] = h;
    g_wpk[1][i >> 4][o * 24 + (i & 15)] =
        __float2bfloat16(v - __bfloat162float(h));
}

__global__ void k_uv(const float* __restrict__ Wg1, const float* __restrict__ Wg2) {
    const int n = blockIdx.x, t = threadIdx.x;
    __shared__ float ss[256];
    ss[t] = g_rowsum[n][t];
    __syncthreads();
    const int g = t >> 5, r = t & 31;
    float u = 0.f, v = 0.f;
#pragma unroll
    for (int i = 0; i < 32; i++) {
        u += Wg1[(g * 32 + r) * 32 + i] * ss[g * 32 + i];
        v += Wg2[(g * 32 + r) * 32 + i] * ss[g * 32 + i];
    }
    g_u[n][t] = u;
    g_v[n][t] = v;
}

// ---- Gram = x x^T (round-7 pipeline, unchanged) ------------------------------
#define GSTRIDE 80u
#define GCH 10240
#define GRAM_SMEM (8 * GCH)

__global__ __launch_bounds__(256, 2) void k_gram() {
    extern __shared__ char sm[];
    const int q = blockIdx.x, n = blockIdx.y, ks = blockIdx.z;
    const int c0 = (q == 1) ? 128 : 0;
    const int d0 = (q == 0) ? 0 : 128;
    const bool diag = (q < 2);
    const int tid = threadIdx.x, lane = tid & 31, wid = tid >> 5;
    const int m0w = (wid & 1) * 64, n0w = (wid >> 1) * 32;
    const uint32_t smb = smem_u32(sm);

    const char* gAh = (const char*)&g_xh[n][c0][0];
    const char* gAl = (const char*)&g_xl[n][c0][0];
    const char* gBh = (const char*)&g_xh[n][d0][0];
    const char* gBl = (const char*)&g_xl[n][d0][0];

    const int lr = tid >> 1, ls = (tid & 1) * 32;
    const int a_r = lane & 15, a_kb = (lane >> 4) * 16;
    const int b_r = (lane & 7) + 8 * (lane >> 4);
    const int b_kb = ((lane >> 3) & 1) * 16;

    float acc[4][4][4];
#pragma unroll
    for (int i = 0; i < 4; i++)
#pragma unroll
        for (int j = 0; j < 4; j++)
#pragma unroll
            for (int p = 0; p < 4; p++) acc[i][j][p] = 0.f;

    const int ck0 = ks * 33;
    const int nck = (ks < 2) ? 33 : 32;
    const uint32_t so = (uint32_t)lr * GSTRIDE + ls;

    auto issueG = [&](int ci, int buf) {
        const size_t go = (size_t)lr * (HW * 2) + (size_t)(ck0 + ci) * 64 + ls;
        const uint32_t aH = smb + (buf * 2 + 0) * GCH + so;
        const uint32_t aL = smb + (buf * 2 + 1) * GCH + so;
        cpa(aH, gAh + go); cpa(aH + 16, gAh + go + 16);
        cpa(aL, gAl + go); cpa(aL + 16, gAl + go + 16);
        if (!diag) {
            const uint32_t bH = smb + 4 * GCH + (buf * 2 + 0) * GCH + so;
            const uint32_t bL = smb + 4 * GCH + (buf * 2 + 1) * GCH + so;
            cpa(bH, gBh + go); cpa(bH + 16, gBh + go + 16);
            cpa(bL, gBl + go); cpa(bL + 16, gBl + go + 16);
        }
    };

    issueG(0, 0);
    CPA_COMMIT();

    for (int ci = 0; ci < nck; ci++) {
        const int buf = ci & 1;
        CPA_WAIT0();
        __syncthreads();
        if (ci < nck - 1) { issueG(ci + 1, buf ^ 1); CPA_COMMIT(); }

        const uint32_t aHb = smb + (buf * 2 + 0) * GCH;
        const uint32_t aLb = smb + (buf * 2 + 1) * GCH;
        const uint32_t bHb = diag ? aHb : smb + 4 * GCH + (buf * 2 + 0) * GCH;
        const uint32_t bLb = diag ? aLb : smb + 4 * GCH + (buf * 2 + 1) * GCH;
#pragma unroll
        for (int kk = 0; kk < 2; kk++) {
            const uint32_t kbo = kk * 32;
            uint32_t a[4][4], bh[4][2], bl[4][2];
#pragma unroll
            for (int mt = 0; mt < 4; mt++)
                ldsm4(a[mt], aHb + (uint32_t)(m0w + mt * 16 + a_r) * GSTRIDE + a_kb + kbo);
#pragma unroll
            for (int nt2 = 0; nt2 < 2; nt2++) {
                const uint32_t ro = (uint32_t)(n0w + nt2 * 16 + b_r) * GSTRIDE + b_kb + kbo;
                uint32_t t[4];
                ldsm4(t, bHb + ro);
                bh[nt2 * 2][0] = t[0]; bh[nt2 * 2][1] = t[1];
                bh[nt2 * 2 + 1][0] = t[2]; bh[nt2 * 2 + 1][1] = t[3];
                ldsm4(t, bLb + ro);
                bl[nt2 * 2][0] = t[0]; bl[nt2 * 2][1] = t[1];
                bl[nt2 * 2 + 1][0] = t[2]; bl[nt2 * 2 + 1][1] = t[3];
            }
#pragma unroll
            for (int mt = 0; mt < 4; mt++)
#pragma unroll
                for (int nt = 0; nt < 4; nt++) {
                    mma_bf16(acc[mt][nt], a[mt], bh[nt]);
                    mma_bf16(acc[mt][nt], a[mt], bl[nt]);
                }
#pragma unroll
            for (int mt = 0; mt < 4; mt++)
                ldsm4(a[mt], aLb + (uint32_t)(m0w + mt * 16 + a_r) * GSTRIDE + a_kb + kbo);
#pragma unroll
            for (int mt = 0; mt < 4; mt++)
#pragma unroll
                for (int nt = 0; nt < 4; nt++)
                    mma_bf16(acc[mt][nt], a[mt], bh[nt]);
        }
        __syncthreads();
    }

    float* gout = &g_gramp[ks][n][0][0];
#pragma unroll
    for (int mt = 0; mt < 4; mt++)
#pragma unroll
        for (int h = 0; h < 2; h++) {
            const int c = c0 + m0w + mt * 16 + (lane >> 2) + h * 8;
#pragma unroll
            for (int nt = 0; nt < 4; nt++) {
                const int d = d0 + n0w + nt * 8 + (lane & 3) * 2;
                const float v0 = acc[mt][nt][h * 2], v1 = acc[mt][nt][h * 2 + 1];
                *(float2*)(gout + (size_t)c * CC + d) = make_float2(v0, v1);
                if (!diag) {
                    gout[(size_t)d * CC + c] = v0;
                    gout[(size_t)(d + 1) * CC + c] = v1;
                }
            }
        }
}

// ---- t7^T packed (split bf16, pre-scaled by 1/896) ---------------------------
__global__ void k_t7(const float* __restrict__ Wg1, const float* __restrict__ bg1,
                     const float* __restrict__ Wg2, const float* __restrict__ bg2,
                     const float* __restrict__ p7w) {
    __shared__ float W1s[32][33], W2s[32][33], Gs[32][33], Ms[32][33];
    const int n = blockIdx.z, g = blockIdx.y, h = blockIdx.x;
    const int tx = threadIdx.x, ty = threadIdx.y;

    W1s[ty][tx] = Wg1[(g * 32 + ty) * 32 + tx];
    W2s[ty][tx] = Wg2[(h * 32 + ty) * 32 + tx];
    Gs[ty][tx]  = g_gramp[0][n][g * 32 + ty][h * 32 + tx]
                + g_gramp[1][n][g * 32 + ty][h * 32 + tx]
                + g_gramp[2][n][g * 32 + ty][h * 32 + tx];
    __syncthreads();

    float m = 0.f;
#pragma unroll
    for (int i = 0; i < 32; i++) m += W1s[ty][i] * Gs[i][tx];
    Ms[ty][tx] = m;
    __syncthreads();

    float t5 = 0.f;
#pragma unroll
    for (int j = 0; j < 32; j++) t5 += Ms[ty][j] * W2s[tx][j];

    const int c = g * 32 + ty, d = h * 32 + tx;
    const float b1 = bg1[c], b2 = bg2[d];
    t5 += b1 * g_v[n][d] + g_u[n][c] * b2 + (float)HW * b1 * b2;
    const float val = p7w[c * 256 + d] * t5 * (1.0f / 896.0f);

    __syncthreads();
    W1s[ty][tx] = val;
    __syncthreads();
    const float tv = W1s[tx][ty];          // t7[c=g*32+tx][d=h*32+ty]
    const int dd = h * 32 + ty, cc = g * 32 + tx;
    __nv_bfloat16 hh = __float2bfloat16(tv);
    g_t7k[n][0][cc >> 4][dd * 24 + (cc & 15)] = hh;
    g_t7k[n][1][cc >> 4][dd * 24 + (cc & 15)] =
        __float2bfloat16(tv - __bfloat162float(hh));
}

// ---- fused: bulk-copy A chunks + B rows, N=128, 512 threads ------------------
#define BROW 272u
#define BHALF 69632u              // 256 * 272
#define FACH 12288u
#define AOFF (2u * BHALF)         // 139264
#define FUSED_SMEM (2 * 69632 + 4 * 12288)   // 188416
#define ACHB 24576u               // hi+lo bulk bytes per A chunk

__global__ __launch_bounds__(512, 1) void k_fused(const float* __restrict__ bp3,
                                                  float* __restrict__ out) {
    extern __shared__ char sm[];
    __shared__ alignas(8) uint64_t s_mb[3];   // A0, A1, B
    const int n = blockIdx.y, sx = blockIdx.x;
    const int tid = threadIdx.x, lane = tid & 31, wid = tid >> 5;
    const int m0w = (wid >> 2) * 64, n0w = (wid & 3) * 32;
    const uint32_t smb = smem_u32(sm);
    const uint32_t mbA0 = smem_u32(&s_mb[0]);
    const uint32_t mbA1 = mbA0 + 8, mbB = mbA0 + 16;
    const bool tail = (sx == 24);
    const uint32_t browbytes = tail ? 128u : 256u;

    auto issueA = [&](int g1, int buf) {   // single thread
        const char* Ah = (g1 < 16) ? (const char*)&g_wpk[0][g1 & 15][0]
                                   : (const char*)&g_t7k[n][0][g1 & 15][0];
        const char* Al = (g1 < 16) ? (const char*)&g_wpk[1][g1 & 15][0]
                                   : (const char*)&g_t7k[n][1][g1 & 15][0];
        const uint32_t mb = buf ? mbA1 : mbA0;
        MBAR_EXPECT(mb, ACHB);
        bulkcp(smb + AOFF + (buf * 2 + 0) * FACH, Ah, FACH, mb);
        bulkcp(smb + AOFF + (buf * 2 + 1) * FACH, Al, FACH, mb);
    };

    if (tid == 0) {
        MBAR_INIT(mbA0, 1); MBAR_INIT(mbA1, 1); MBAR_INIT(mbB, 1);
    }
    __syncthreads();
    if (tid == 0) {
        MBAR_EXPECT(mbB, 512u * browbytes);
        issueA(0, 0);
    }
    __syncthreads();
    {   // B: 256 rows x (hi,lo), one bulk per row
        const int half = tid >> 8, r = tid & 255;
        const char* src = (half ? (const char*)&g_xl[n][r][0]
                                : (const char*)&g_xh[n][r][0]) + (size_t)sx * 256;
        bulkcp(smb + half * BHALF + (uint32_t)r * BROW, src, browbytes, mbB);
    }

    float acc[4][4][4];
#pragma unroll
    for (int i = 0; i < 4; i++)
#pragma unroll
        for (int j = 0; j < 4; j++)
#pragma unroll
            for (int p = 0; p < 4; p++) acc[i][j][p] = 0.f;

    const int a_r = lane & 15, a_kb = (lane >> 4) * 16;
    const int bt_r = (lane & 7) + 8 * ((lane >> 3) & 1);
    const int bt_nb = (lane >> 4) * 16;
    int ph0 = 0, ph1 = 0;

    for (int g = 0; g < 32; g++) {
        const int buf = g & 1;
        __syncthreads();                           // prev chunk fully consumed
        if (g < 31 && tid == 0) issueA(g + 1, buf ^ 1);
        if (buf == 0) { MBAR_WAIT(mbA0, ph0); ph0 ^= 1; }
        else          { MBAR_WAIT(mbA1, ph1); ph1 ^= 1; }
        if (g == 0) MBAR_WAIT(mbB, 0);

        if (g == 16) {
            // stage0 epilogue: t6 = max(t3 + bias, sin(pi/2 x)); rewrite B
#pragma unroll
            for (int mt = 0; mt < 4; mt++)
#pragma unroll
                for (int h = 0; h < 2; h++) {
                    const int c = m0w + mt * 16 + (lane >> 2) + h * 8;
                    const float bias = __ldg(&bp3[c]);
#pragma unroll
                    for (int nt = 0; nt < 4; nt++) {
                        const int j = n0w + nt * 8 + (lane & 3) * 2;
                        uint32_t* ph = (uint32_t*)(sm + (uint32_t)c * BROW + j * 2);
                        uint32_t* pl = (uint32_t*)(sm + BHALF + (uint32_t)c * BROW + j * 2);
                        const uint32_t vh = *ph, vl = *pl;
                        const float x0 = bflo(vh) + bflo(vl);
                        const float x1 = bfhi(vh) + bfhi(vl);
                        const float t60 = fmaxf(acc[mt][nt][h * 2] + bias,
                                                __sinf(PI_HALF * x0));
                        const float t61 = fmaxf(acc[mt][nt][h * 2 + 1] + bias,
                                                __sinf(PI_HALF * x1));
                        __nv_bfloat16 h0 = __float2bfloat16(t60);
                        __nv_bfloat16 h1 = __float2bfloat16(t61);
                        *ph = pk2(h0, h1);
                        *pl = pk2(__float2bfloat16(t60 - __bfloat162float(h0)),
                                  __float2bfloat16(t61 - __bfloat162float(h1)));
                        acc[mt][nt][h * 2] = 0.f;
                        acc[mt][nt][h * 2 + 1] = 0.f;
                    }
                }
            __syncthreads();
        }

        const uint32_t aHb = smb + AOFF + (buf * 2 + 0) * FACH;
        const uint32_t aLb = smb + AOFF + (buf * 2 + 1) * FACH;
        const int kg = (g & 15) * 16;
        uint32_t a[4][4], bh[4][2], bl[4][2];
#pragma unroll
        for (int mt = 0; mt < 4; mt++)
            ldsm4(a[mt], aHb + (uint32_t)(m0w + mt * 16 + a_r) * 48u + a_kb);
#pragma unroll
        for (int nt2 = 0; nt2 < 2; nt2++) {
            const uint32_t ro = (uint32_t)(kg + bt_r) * BROW
                              + (uint32_t)(n0w + nt2 * 16) * 2 + bt_nb;
            uint32_t t[4];
            ldsm4t(t, smb + ro);
            bh[nt2 * 2][0] = t[0]; bh[nt2 * 2][1] = t[1];
            bh[nt2 * 2 + 1][0] = t[2]; bh[nt2 * 2 + 1][1] = t[3];
            ldsm4t(t, smb + BHALF + ro);
            bl[nt2 * 2][0] = t[0]; bl[nt2 * 2][1] = t[1];
            bl[nt2 * 2 + 1][0] = t[2]; bl[nt2 * 2 + 1][1] = t[3];
        }
#pragma unroll
        for (int mt = 0; mt < 4; mt++)
#pragma unroll
            for (int nt = 0; nt < 4; nt++) {
                mma_bf16(acc[mt][nt], a[mt], bh[nt]);
                mma_bf16(acc[mt][nt], a[mt], bl[nt]);
            }
#pragma unroll
        for (int mt = 0; mt < 4; mt++)
            ldsm4(a[mt], aLb + (uint32_t)(m0w + mt * 16 + a_r) * 48u + a_kb);
#pragma unroll
        for (int mt = 0; mt < 4; mt++)
#pragma unroll
            for (int nt = 0; nt < 4; nt++)
                mma_bf16(acc[mt][nt], a[mt], bh[nt]);
    }

    float* ob = out + (size_t)n * CC * HW + (size_t)sx * 128;
#pragma unroll
    for (int mt = 0; mt < 4; mt++)
#pragma unroll
        for (int h = 0; h < 2; h++) {
            const int d = m0w + mt * 16 + (lane >> 2) + h * 8;
#pragma unroll
            for (int nt = 0; nt < 4; nt++) {
                const int j = n0w + nt * 8 + (lane & 3) * 2;
                if (!tail || j < 64)
                    *(float2*)(ob + (size_t)d * HW + j) =
                        make_float2(acc[mt][nt][h * 2], acc[mt][nt][h * 2 + 1]);
            }
        }
}

extern "C" void kernel_launch(void* const* d_in, const int* in_sizes, int n_in,
                              void* d_out, int out_size) {
    (void)in_sizes; (void)n_in; (void)out_size;
    const float* x   = (const float*)d_in[0];
    const float* Wp3 = (const float*)d_in[1];
    const float* bp3 = (const float*)d_in[2];
    const float* Wg1 = (const float*)d_in[3];
    const float* bg1 = (const float*)d_in[4];
    const float* Wg2 = (const float*)d_in[5];
    const float* bg2 = (const float*)d_in[6];
    const float* p7w = (const float*)d_in[7];
    float* out = (float*)d_out;

    cudaFuncSetAttribute(k_gram,  cudaFuncAttributeMaxDynamicSharedMemorySize, GRAM_SMEM);
    cudaFuncSetAttribute(k_fused, cudaFuncAttributeMaxDynamicSharedMemorySize, FUSED_SMEM);

    k_wprep<<<256, 256>>>(Wp3);
    k_prep<<<dim3(256, 32), 256>>>(x);
    k_uv<<<32, 256>>>(Wg1, Wg2);
    k_gram<<<dim3(3, 32, 3), 256, GRAM_SMEM>>>();
    k_t7<<<dim3(8, 8, 32), dim3(32, 32)>>>(Wg1, bg1, Wg2, bg2, p7w);
    k_fused<<<dim3(25, 32), 512, FUSED_SMEM>>>(bp3, out);
}